// round 7
// baseline (speedup 1.0000x reference)
#include <cuda_runtime.h>

#define N_USERS 200000
#define N_ITEMS 100000
#define N_NODES (N_USERS + N_ITEMS)
#define N_EDGES_MAX 1250000
#define DIM 64
#define EPS 1e-12f
#define NODES_PER_BLOCK 128

// ---------------------------------------------------------------------------
// Scratch (device globals — no allocations allowed)
// g_counts[N_NODES] = histogram; g_counts[N_NODES] (last slot) = global base.
// ---------------------------------------------------------------------------
__device__ int  g_counts[N_NODES + 1];
__device__ int  g_offsets[N_NODES];
__device__ int  g_rank[N_EDGES_MAX];   // per-edge rank among same-dst edges
__device__ int2 g_edges[N_EDGES_MAX];  // {src, weight-bits} in dst-grouped order

// ---------------------------------------------------------------------------
// 1) histogram of dst; atomic return value = edge's rank among same-dst edges
// ---------------------------------------------------------------------------
__global__ void hist_rank_kernel(const int* __restrict__ dst, int n_edges) {
    int i  = blockIdx.x * blockDim.x + threadIdx.x;
    int e0 = i * 4;
    if (e0 + 3 < n_edges) {
        int4 d = *(const int4*)(dst + e0);
        int r0 = atomicAdd(&g_counts[d.x], 1);
        int r1 = atomicAdd(&g_counts[d.y], 1);
        int r2 = atomicAdd(&g_counts[d.z], 1);
        int r3 = atomicAdd(&g_counts[d.w], 1);
        *(int4*)(g_rank + e0) = make_int4(r0, r1, r2, r3);
    } else {
        for (int e = e0; e < n_edges; ++e)
            g_rank[e] = atomicAdd(&g_counts[dst[e]], 1);
    }
}

// ---------------------------------------------------------------------------
// 2) per-block scan of counts; block base via one global atomicAdd.
// ---------------------------------------------------------------------------
__global__ void base_assign_kernel() {
    __shared__ int warpTot[8];
    __shared__ int blockBase;
    int t = threadIdx.x;
    int i = blockIdx.x * blockDim.x + t;
    int lane = t & 31, wid = t >> 5;

    int c = (i < N_NODES) ? g_counts[i] : 0;

    int inc = c;
    #pragma unroll
    for (int o = 1; o < 32; o <<= 1) {
        int x = __shfl_up_sync(0xffffffffu, inc, o);
        if (lane >= o) inc += x;
    }
    if (lane == 31) warpTot[wid] = inc;
    __syncthreads();
    if (wid == 0) {
        int wv = (lane < 8) ? warpTot[lane] : 0;
        #pragma unroll
        for (int o = 1; o < 8; o <<= 1) {
            int x = __shfl_up_sync(0xffffffffu, wv, o);
            if (lane >= o) wv += x;
        }
        if (lane < 8) warpTot[lane] = wv;
        if (lane == 7) blockBase = atomicAdd(&g_counts[N_NODES], wv);
    }
    __syncthreads();

    int ex = ((wid > 0) ? warpTot[wid - 1] : 0) + inc - c;
    if (i < N_NODES) g_offsets[i] = blockBase + ex;
}

// ---------------------------------------------------------------------------
// 3) atomic-free scatter: pos = offsets[dst] + rank. 4 edges/thread.
// ---------------------------------------------------------------------------
__global__ void scatter_pack_kernel(const int*   __restrict__ src,
                                    const int*   __restrict__ dst,
                                    const float* __restrict__ w,
                                    int n_edges) {
    int i  = blockIdx.x * blockDim.x + threadIdx.x;
    int e0 = i * 4;
    if (e0 + 3 < n_edges) {
        int4   s  = *(const int4*)  (src + e0);
        int4   d  = *(const int4*)  (dst + e0);
        float4 ww = *(const float4*)(w   + e0);
        int4   r  = *(const int4*)  (g_rank + e0);
        int p0 = __ldg(&g_offsets[d.x]) + r.x;
        int p1 = __ldg(&g_offsets[d.y]) + r.y;
        int p2 = __ldg(&g_offsets[d.z]) + r.z;
        int p3 = __ldg(&g_offsets[d.w]) + r.w;
        g_edges[p0] = make_int2(s.x, __float_as_int(ww.x));
        g_edges[p1] = make_int2(s.y, __float_as_int(ww.y));
        g_edges[p2] = make_int2(s.z, __float_as_int(ww.z));
        g_edges[p3] = make_int2(s.w, __float_as_int(ww.w));
    } else {
        for (int e = e0; e < n_edges; ++e) {
            int p = __ldg(&g_offsets[dst[e]]) + g_rank[e];
            g_edges[p] = make_int2(src[e], __float_as_int(w[e]));
        }
    }
}

// ---------------------------------------------------------------------------
// 4) 8 lanes per node, DYNAMIC node assignment via per-block smem ticket:
//    groups that finish a light node immediately pop the next one, so lanes
//    stay busy instead of idling at max-degree-of-the-warp.
// ---------------------------------------------------------------------------
__global__ __launch_bounds__(256) void aggregate_kernel(
        const float* __restrict__ ue,
        const float* __restrict__ ie,
        float*       __restrict__ out) {
    __shared__ int s_next;
    int t = threadIdx.x;
    if (t == 0) s_next = 0;
    __syncthreads();

    int l = t & 7;
    unsigned mask = 0xFFu << (((t >> 3) & 3) * 8);

    int base_node = blockIdx.x * NODES_PER_BLOCK;
    int limit = min(NODES_PER_BLOCK, N_NODES - base_node);

    for (;;) {
        int idx = 0;
        if (l == 0) idx = atomicAdd(&s_next, 1);
        idx = __shfl_sync(mask, idx, 0, 8);
        if (idx >= limit) break;
        int node = base_node + idx;

        int beg = __ldg(&g_offsets[node]);
        int end = beg + __ldg(&g_counts[node]);

        float a0 = 0.f, a1 = 0.f, a2 = 0.f, a3 = 0.f;
        float b0 = 0.f, b1 = 0.f, b2 = 0.f, b3 = 0.f;

        for (int base = beg; base < end; base += 8) {
            int m = min(8, end - base);
            int2 ew = (l < m) ? __ldg(&g_edges[base + l]) : make_int2(0, 0);

            int j = 0;
            for (; j + 2 <= m; j += 2) {
                int s0 = __shfl_sync(mask, ew.x, j,     8);
                int w0 = __shfl_sync(mask, ew.y, j,     8);
                int s1 = __shfl_sync(mask, ew.x, j + 1, 8);
                int w1 = __shfl_sync(mask, ew.y, j + 1, 8);
                const float4* h0 = (const float4*)((s0 < N_USERS)
                    ? (ue + (long long)s0 * DIM)
                    : (ie + (long long)(s0 - N_USERS) * DIM));
                const float4* h1 = (const float4*)((s1 < N_USERS)
                    ? (ue + (long long)s1 * DIM)
                    : (ie + (long long)(s1 - N_USERS) * DIM));
                float4 v0a = __ldg(h0 + l);
                float4 v0b = __ldg(h0 + l + 8);
                float4 v1a = __ldg(h1 + l);
                float4 v1b = __ldg(h1 + l + 8);
                float  f0 = __int_as_float(w0);
                float  f1 = __int_as_float(w1);
                a0 = fmaf(f0, v0a.x, a0);  a1 = fmaf(f0, v0a.y, a1);
                a2 = fmaf(f0, v0a.z, a2);  a3 = fmaf(f0, v0a.w, a3);
                b0 = fmaf(f0, v0b.x, b0);  b1 = fmaf(f0, v0b.y, b1);
                b2 = fmaf(f0, v0b.z, b2);  b3 = fmaf(f0, v0b.w, b3);
                a0 = fmaf(f1, v1a.x, a0);  a1 = fmaf(f1, v1a.y, a1);
                a2 = fmaf(f1, v1a.z, a2);  a3 = fmaf(f1, v1a.w, a3);
                b0 = fmaf(f1, v1b.x, b0);  b1 = fmaf(f1, v1b.y, b1);
                b2 = fmaf(f1, v1b.z, b2);  b3 = fmaf(f1, v1b.w, b3);
            }
            if (j < m) {
                int s0 = __shfl_sync(mask, ew.x, j, 8);
                int w0 = __shfl_sync(mask, ew.y, j, 8);
                const float4* h0 = (const float4*)((s0 < N_USERS)
                    ? (ue + (long long)s0 * DIM)
                    : (ie + (long long)(s0 - N_USERS) * DIM));
                float4 v0a = __ldg(h0 + l);
                float4 v0b = __ldg(h0 + l + 8);
                float  f0 = __int_as_float(w0);
                a0 = fmaf(f0, v0a.x, a0);  a1 = fmaf(f0, v0a.y, a1);
                a2 = fmaf(f0, v0a.z, a2);  a3 = fmaf(f0, v0a.w, a3);
                b0 = fmaf(f0, v0b.x, b0);  b1 = fmaf(f0, v0b.y, b1);
                b2 = fmaf(f0, v0b.z, b2);  b3 = fmaf(f0, v0b.w, b3);
            }
        }

        float ss = a0*a0 + a1*a1 + a2*a2 + a3*a3
                 + b0*b0 + b1*b1 + b2*b2 + b3*b3;
        #pragma unroll
        for (int off = 4; off; off >>= 1)
            ss += __shfl_xor_sync(mask, ss, off, 8);

        float scale = 1.0f / fmaxf(sqrtf(ss), EPS);
        float4* orow = (float4*)(out + (long long)node * DIM);
        orow[l]     = make_float4(a0 * scale, a1 * scale, a2 * scale, a3 * scale);
        orow[l + 8] = make_float4(b0 * scale, b1 * scale, b2 * scale, b3 * scale);
    }
}

// ---------------------------------------------------------------------------
// Launch
// ---------------------------------------------------------------------------
extern "C" void kernel_launch(void* const* d_in, const int* in_sizes, int n_in,
                              void* d_out, int out_size) {
    const float* ue  = (const float*)d_in[0];
    const float* ie  = (const float*)d_in[1];
    const int*   src = (const int*)  d_in[2];
    const int*   dst = (const int*)  d_in[3];
    const float* w   = (const float*)d_in[4];
    float*       out = (float*)d_out;

    const int E  = in_sizes[2];
    const int E4 = (E + 3) / 4;

    void* counts_ptr = nullptr;
    cudaGetSymbolAddress(&counts_ptr, g_counts);
    cudaMemsetAsync(counts_ptr, 0, (N_NODES + 1) * sizeof(int));

    hist_rank_kernel<<<(E4 + 255) / 256, 256>>>(dst, E);
    base_assign_kernel<<<(N_NODES + 255) / 256, 256>>>();
    scatter_pack_kernel<<<(E4 + 255) / 256, 256>>>(src, dst, w, E);

    int agg_blocks = (N_NODES + NODES_PER_BLOCK - 1) / NODES_PER_BLOCK;
    aggregate_kernel<<<agg_blocks, 256>>>(ue, ie, out);
}

// round 8
// speedup vs baseline: 1.1373x; 1.1373x over previous
#include <cuda_runtime.h>

#define N_USERS 200000
#define N_ITEMS 100000
#define N_NODES (N_USERS + N_ITEMS)
#define N_EDGES_MAX 1250000
#define DIM 64
#define EPS 1e-12f

// ---------------------------------------------------------------------------
// Scratch (device globals — no allocations allowed)
// g_counts[N_NODES] = histogram; g_counts[N_NODES] (last slot) = global base.
// g_meta[node] = {segment offset, count} packed for a single 8B load.
// ---------------------------------------------------------------------------
__device__ int  g_counts[N_NODES + 1];
__device__ int2 g_meta[N_NODES];
__device__ int  g_rank[N_EDGES_MAX];   // per-edge rank among same-dst edges
__device__ int2 g_edges[N_EDGES_MAX];  // {src, weight-bits} in dst-grouped order

// ---------------------------------------------------------------------------
// 1) histogram of dst; atomic return value = edge's rank among same-dst edges
// ---------------------------------------------------------------------------
__global__ void hist_rank_kernel(const int* __restrict__ dst, int n_edges) {
    int i  = blockIdx.x * blockDim.x + threadIdx.x;
    int e0 = i * 4;
    if (e0 + 3 < n_edges) {
        int4 d = *(const int4*)(dst + e0);
        int r0 = atomicAdd(&g_counts[d.x], 1);
        int r1 = atomicAdd(&g_counts[d.y], 1);
        int r2 = atomicAdd(&g_counts[d.z], 1);
        int r3 = atomicAdd(&g_counts[d.w], 1);
        *(int4*)(g_rank + e0) = make_int4(r0, r1, r2, r3);
    } else {
        for (int e = e0; e < n_edges; ++e)
            g_rank[e] = atomicAdd(&g_counts[dst[e]], 1);
    }
}

// ---------------------------------------------------------------------------
// 2) per-block scan of counts; block base via one global atomicAdd.
//    Writes packed {offset, count}.
// ---------------------------------------------------------------------------
__global__ void base_assign_kernel() {
    __shared__ int warpTot[8];
    __shared__ int blockBase;
    int t = threadIdx.x;
    int i = blockIdx.x * blockDim.x + t;
    int lane = t & 31, wid = t >> 5;

    int c = (i < N_NODES) ? g_counts[i] : 0;

    int inc = c;
    #pragma unroll
    for (int o = 1; o < 32; o <<= 1) {
        int x = __shfl_up_sync(0xffffffffu, inc, o);
        if (lane >= o) inc += x;
    }
    if (lane == 31) warpTot[wid] = inc;
    __syncthreads();
    if (wid == 0) {
        int wv = (lane < 8) ? warpTot[lane] : 0;
        #pragma unroll
        for (int o = 1; o < 8; o <<= 1) {
            int x = __shfl_up_sync(0xffffffffu, wv, o);
            if (lane >= o) wv += x;
        }
        if (lane < 8) warpTot[lane] = wv;
        if (lane == 7) blockBase = atomicAdd(&g_counts[N_NODES], wv);
    }
    __syncthreads();

    int ex = ((wid > 0) ? warpTot[wid - 1] : 0) + inc - c;
    if (i < N_NODES) g_meta[i] = make_int2(blockBase + ex, c);
}

// ---------------------------------------------------------------------------
// 3) atomic-free scatter: pos = meta[dst].x + rank. 2 edges/thread.
// ---------------------------------------------------------------------------
__global__ void scatter_pack_kernel(const int*   __restrict__ src,
                                    const int*   __restrict__ dst,
                                    const float* __restrict__ w,
                                    int n_edges) {
    int i  = blockIdx.x * blockDim.x + threadIdx.x;
    int e0 = i * 2;
    if (e0 + 1 < n_edges) {
        int2   s  = *(const int2*)  (src + e0);
        int2   d  = *(const int2*)  (dst + e0);
        float2 ww = *(const float2*)(w   + e0);
        int2   r  = *(const int2*)  (g_rank + e0);
        int p0 = __ldg(&g_meta[d.x].x) + r.x;
        int p1 = __ldg(&g_meta[d.y].x) + r.y;
        g_edges[p0] = make_int2(s.x, __float_as_int(ww.x));
        g_edges[p1] = make_int2(s.y, __float_as_int(ww.y));
    } else {
        for (int e = e0; e < n_edges; ++e) {
            int p = __ldg(&g_meta[dst[e]].x) + g_rank[e];
            g_edges[p] = make_int2(src[e], __float_as_int(w[e]));
        }
    }
}

// ---------------------------------------------------------------------------
// 4) 8 lanes per node (static, 4 nodes/warp), 2x float4 per lane:
//    gather + aggregate + L2-normalize + store.
// ---------------------------------------------------------------------------
__global__ __launch_bounds__(256) void aggregate_kernel(
        const float* __restrict__ ue,
        const float* __restrict__ ie,
        float*       __restrict__ out) {
    int gid  = blockIdx.x * blockDim.x + threadIdx.x;
    int node = gid >> 3;
    int l    = gid & 7;
    if (node >= N_NODES) return;

    unsigned mask = 0xFFu << (((threadIdx.x >> 3) & 3) * 8);

    int2 meta = __ldg(&g_meta[node]);
    int beg = meta.x;
    int end = beg + meta.y;

    float a0 = 0.f, a1 = 0.f, a2 = 0.f, a3 = 0.f;
    float b0 = 0.f, b1 = 0.f, b2 = 0.f, b3 = 0.f;

    for (int base = beg; base < end; base += 8) {
        int m = min(8, end - base);
        int2 ew = (l < m) ? __ldg(&g_edges[base + l]) : make_int2(0, 0);

        int j = 0;
        for (; j + 2 <= m; j += 2) {
            int s0 = __shfl_sync(mask, ew.x, j,     8);
            int w0 = __shfl_sync(mask, ew.y, j,     8);
            int s1 = __shfl_sync(mask, ew.x, j + 1, 8);
            int w1 = __shfl_sync(mask, ew.y, j + 1, 8);
            const float4* h0 = (const float4*)((s0 < N_USERS)
                ? (ue + (long long)s0 * DIM)
                : (ie + (long long)(s0 - N_USERS) * DIM));
            const float4* h1 = (const float4*)((s1 < N_USERS)
                ? (ue + (long long)s1 * DIM)
                : (ie + (long long)(s1 - N_USERS) * DIM));
            float4 v0a = __ldg(h0 + l);
            float4 v0b = __ldg(h0 + l + 8);
            float4 v1a = __ldg(h1 + l);
            float4 v1b = __ldg(h1 + l + 8);
            float  f0 = __int_as_float(w0);
            float  f1 = __int_as_float(w1);
            a0 = fmaf(f0, v0a.x, a0);  a1 = fmaf(f0, v0a.y, a1);
            a2 = fmaf(f0, v0a.z, a2);  a3 = fmaf(f0, v0a.w, a3);
            b0 = fmaf(f0, v0b.x, b0);  b1 = fmaf(f0, v0b.y, b1);
            b2 = fmaf(f0, v0b.z, b2);  b3 = fmaf(f0, v0b.w, b3);
            a0 = fmaf(f1, v1a.x, a0);  a1 = fmaf(f1, v1a.y, a1);
            a2 = fmaf(f1, v1a.z, a2);  a3 = fmaf(f1, v1a.w, a3);
            b0 = fmaf(f1, v1b.x, b0);  b1 = fmaf(f1, v1b.y, b1);
            b2 = fmaf(f1, v1b.z, b2);  b3 = fmaf(f1, v1b.w, b3);
        }
        if (j < m) {
            int s0 = __shfl_sync(mask, ew.x, j, 8);
            int w0 = __shfl_sync(mask, ew.y, j, 8);
            const float4* h0 = (const float4*)((s0 < N_USERS)
                ? (ue + (long long)s0 * DIM)
                : (ie + (long long)(s0 - N_USERS) * DIM));
            float4 v0a = __ldg(h0 + l);
            float4 v0b = __ldg(h0 + l + 8);
            float  f0 = __int_as_float(w0);
            a0 = fmaf(f0, v0a.x, a0);  a1 = fmaf(f0, v0a.y, a1);
            a2 = fmaf(f0, v0a.z, a2);  a3 = fmaf(f0, v0a.w, a3);
            b0 = fmaf(f0, v0b.x, b0);  b1 = fmaf(f0, v0b.y, b1);
            b2 = fmaf(f0, v0b.z, b2);  b3 = fmaf(f0, v0b.w, b3);
        }
    }

    float ss = a0*a0 + a1*a1 + a2*a2 + a3*a3
             + b0*b0 + b1*b1 + b2*b2 + b3*b3;
    #pragma unroll
    for (int off = 4; off; off >>= 1)
        ss += __shfl_xor_sync(mask, ss, off, 8);

    float scale = 1.0f / fmaxf(sqrtf(ss), EPS);
    float4* orow = (float4*)(out + (long long)node * DIM);
    orow[l]     = make_float4(a0 * scale, a1 * scale, a2 * scale, a3 * scale);
    orow[l + 8] = make_float4(b0 * scale, b1 * scale, b2 * scale, b3 * scale);
}

// ---------------------------------------------------------------------------
// Launch
// ---------------------------------------------------------------------------
extern "C" void kernel_launch(void* const* d_in, const int* in_sizes, int n_in,
                              void* d_out, int out_size) {
    const float* ue  = (const float*)d_in[0];
    const float* ie  = (const float*)d_in[1];
    const int*   src = (const int*)  d_in[2];
    const int*   dst = (const int*)  d_in[3];
    const float* w   = (const float*)d_in[4];
    float*       out = (float*)d_out;

    const int E  = in_sizes[2];
    const int E4 = (E + 3) / 4;
    const int E2 = (E + 1) / 2;

    void* counts_ptr = nullptr;
    cudaGetSymbolAddress(&counts_ptr, g_counts);
    cudaMemsetAsync(counts_ptr, 0, (N_NODES + 1) * sizeof(int));

    hist_rank_kernel<<<(E4 + 255) / 256, 256>>>(dst, E);
    base_assign_kernel<<<(N_NODES + 255) / 256, 256>>>();
    scatter_pack_kernel<<<(E2 + 255) / 256, 256>>>(src, dst, w, E);

    long long nt = (long long)N_NODES * 8;
    aggregate_kernel<<<(int)((nt + 255) / 256), 256>>>(ue, ie, out);
}